// round 12
// baseline (speedup 1.0000x reference)
#include <cuda_runtime.h>

// WeightedDistanceTransform — 3-kernel pipeline (R7 bodies, PDL-overlapped boundaries).
// k1: bitmask pack (ballot) -> 1-bit mask scratch
// k2: g^2 on the fly (clz/ffs) + exact early-exit vertical min-plus -> dt + atomicMax
//     [PDL: launches during k1, grid-syncs before reading maskbuf]
// k3: inverted normalize (mx - dt)/mx
//     [PDL: launches during k2, grid-syncs before reading dt/max]

#define HH 256
#define WW 256
#define NPIX (HH * WW)
#define BIG 512
#define MAXSLICES 64
#define WPR 8
#define SLICE_WORDS (HH * WPR)        // 2048

__device__ unsigned int maskbuf[MAXSLICES * SLICE_WORDS];
__device__ unsigned int mx_bits[MAXSLICES];

// ---------------- Kernel 1: mask pack (R7 version, verbatim) ----------------
#define K1_THREADS 256

__global__ __launch_bounds__(K1_THREADS)
void k1_mask(const float* __restrict__ in) {
    const int slice = blockIdx.x >> 4;
    const int rb    = blockIdx.x & 15;
    const int tid   = threadIdx.x;

    if (rb == 0 && tid == 0) mx_bits[slice] = 0u;        // reset before k2

    const float4* s4 = reinterpret_cast<const float4*>(in)
                     + (size_t)slice * (NPIX / 4) + (size_t)rb * 1024 + tid * 4;
    float4 a = s4[0], b = s4[1], c = s4[2], d = s4[3];
    unsigned m = 0;
    m |= (a.x != 0.0f) << 0;  m |= (a.y != 0.0f) << 1;
    m |= (a.z != 0.0f) << 2;  m |= (a.w != 0.0f) << 3;
    m |= (b.x != 0.0f) << 4;  m |= (b.y != 0.0f) << 5;
    m |= (b.z != 0.0f) << 6;  m |= (b.w != 0.0f) << 7;
    m |= (c.x != 0.0f) << 8;  m |= (c.y != 0.0f) << 9;
    m |= (c.z != 0.0f) << 10; m |= (c.w != 0.0f) << 11;
    m |= (d.x != 0.0f) << 12; m |= (d.y != 0.0f) << 13;
    m |= (d.z != 0.0f) << 14; m |= (d.w != 0.0f) << 15;
    unsigned other = __shfl_xor_sync(0xffffffffu, m, 1);
    if ((tid & 1) == 0) {
        maskbuf[slice * SLICE_WORDS + rb * 128 + (tid >> 1)] = m | (other << 16);
    }
}

// ---------------- Kernel 2: g^2 + vertical min-plus (R7 body + PDL sync) ----------------
#define K2_COLS 16
#define K2_THREADS 512

__global__ __launch_bounds__(K2_THREADS)
void k2_passB(float* __restrict__ out) {
    __shared__ unsigned int M[SLICE_WORDS];       // 8 KB: whole-slice bitmask
    __shared__ unsigned int g2[HH * K2_COLS];     // 16 KB: g^2 tile [row][col]
    __shared__ float red[K2_THREADS / 32];        // 16 warps

    const int slice = blockIdx.x >> 4;            // 16 strips per slice
    const int st    = blockIdx.x & 15;
    const int c0    = st * K2_COLS;
    const int tid   = threadIdx.x;

    // PDL: wait for k1's maskbuf writes + mx_bits reset to be visible
    cudaGridDependencySynchronize();

    // load slice bitmask: 4 words/thread
    {
        const unsigned int* src = maskbuf + slice * SLICE_WORDS;
        #pragma unroll
        for (int k = 0; k < SLICE_WORDS / K2_THREADS; ++k)
            M[k * K2_THREADS + tid] = src[k * K2_THREADS + tid];
    }
    __syncthreads();

    // compute g^2 for the strip: 8 px/thread via clz/ffs on row bitmask
    #pragma unroll
    for (int it = 0; it < (HH * K2_COLS) / K2_THREADS; ++it) {
        int i = it * K2_THREADS + tid;
        int r = i >> 4;
        int w = c0 + (i & 15);
        const unsigned int* Mr = M + r * WPR;
        int ci = w >> 5, b = w & 31;

        int ld = BIG;                                          // nearest zero <= w
        unsigned lmask = (b == 31) ? 0xffffffffu : ((2u << b) - 1u);
        unsigned z = (~Mr[ci]) & lmask;
        if (z) {
            ld = b - (31 - __clz(z));
        } else {
            for (int cj = ci - 1; cj >= 0; --cj) {
                unsigned zz = ~Mr[cj];
                if (zz) { ld = (ci - cj) * 32 + b - (31 - __clz(zz)); break; }
            }
        }
        int rd = BIG;                                          // nearest zero >= w
        z = (~Mr[ci]) >> b;
        if (z) {
            rd = __ffs(z) - 1;
        } else {
            for (int cj = ci + 1; cj < WPR; ++cj) {
                unsigned zz = ~Mr[cj];
                if (zz) { rd = cj * 32 + (__ffs(zz) - 1) - w; break; }
            }
        }
        int g = min(min(ld, rd), BIG);
        g2[r * K2_COLS + (i & 15)] = (unsigned)(g * g);
    }
    __syncthreads();

    const float wts[3] = {0.5f, 1.0f, 2.0f};
    const float wc = wts[slice % 3];
    float* dst = out + (size_t)slice * NPIX;

    float lmax = 0.0f;
    #pragma unroll
    for (int it = 0; it < (HH * K2_COLS) / K2_THREADS; ++it) {
        int i = it * K2_THREADS + tid;
        int r = i >> 4, c = i & 15;
        int best = (int)g2[r * K2_COLS + c];
        for (int d = 1; d < HH; ++d) {
            int dd = d * d;
            if (dd >= best) break;                // exact: candidates are >= d^2
            int up = r - d, dn = r + d;
            if (up >= 0) best = min(best, (int)g2[up * K2_COLS + c] + dd);
            if (dn < HH) best = min(best, (int)g2[dn * K2_COLS + c] + dd);
        }
        float dt = wc * sqrtf((float)best);
        dst[r * WW + c0 + c] = dt;
        lmax = fmaxf(lmax, dt);
    }

    #pragma unroll
    for (int o = 16; o; o >>= 1) lmax = fmaxf(lmax, __shfl_xor_sync(0xffffffffu, lmax, o));
    if ((tid & 31) == 0) red[tid >> 5] = lmax;
    __syncthreads();
    if (tid < 16) {
        float v = red[tid];
        #pragma unroll
        for (int o = 8; o; o >>= 1) v = fmaxf(v, __shfl_xor_sync(0x0000ffffu, v, o, 16));
        if (tid == 0) atomicMax(&mx_bits[slice], __float_as_uint(v));  // dt>=0: bit-monotone
    }
}

// ---------------- Kernel 3: normalize (R7 body + PDL sync) ----------------
#define K3_THREADS 256

__global__ __launch_bounds__(K3_THREADS)
void k3_norm(float* __restrict__ out) {
    const int slice = blockIdx.x >> 4;
    const int bl    = blockIdx.x & 15;

    // PDL: wait for k2's dt writes + atomicMax to be visible
    cudaGridDependencySynchronize();

    const float mx  = __uint_as_float(mx_bits[slice]);
    const float inv = (mx > 0.0f) ? (1.0f / mx) : 0.0f;   // mx==0 -> dt==0 -> out 0

    float4* p = reinterpret_cast<float4*>(out) + (size_t)slice * (NPIX / 4) + bl * 1024;
    #pragma unroll
    for (int k = 0; k < 4; ++k) {
        int j = k * K3_THREADS + threadIdx.x;
        float4 v = p[j];
        v.x = (mx - v.x) * inv;
        v.y = (mx - v.y) * inv;
        v.z = (mx - v.z) * inv;
        v.w = (mx - v.w) * inv;
        p[j] = v;
    }
}

// ---------------- launch: PDL-chained ----------------
static void launch_pdl(void* func, dim3 grid, dim3 block, void** args) {
    cudaLaunchConfig_t cfg = {};
    cfg.gridDim  = grid;
    cfg.blockDim = block;
    cfg.dynamicSmemBytes = 0;
    cfg.stream = 0;                                   // captured stream
    cudaLaunchAttribute attr[1];
    attr[0].id = cudaLaunchAttributeProgrammaticStreamSerialization;
    attr[0].val.programmaticStreamSerializationAllowed = 1;
    cfg.attrs = attr;
    cfg.numAttrs = 1;
    cudaLaunchKernelExC(&cfg, func, args);
}

extern "C" void kernel_launch(void* const* d_in, const int* in_sizes, int n_in,
                              void* d_out, int out_size) {
    const float* in = (const float*)d_in[0];
    float* out = (float*)d_out;
    const int nslices = in_sizes[0] / NPIX;       // 48 for [16,3,256,256]

    k1_mask<<<nslices * 16, K1_THREADS>>>(in);

    void* a2[] = { (void*)&out };
    launch_pdl((void*)k2_passB, dim3(nslices * 16), dim3(K2_THREADS), a2);

    void* a3[] = { (void*)&out };
    launch_pdl((void*)k3_norm, dim3(nslices * 16), dim3(K3_THREADS), a3);
}

// round 13
// speedup vs baseline: 1.0087x; 1.0087x over previous
#include <cuda_runtime.h>

// WeightedDistanceTransform — 2-kernel pipeline, last-CTA normalize epilogue
// with single-thread release/acquire fences (threadFenceReduction pattern).
// k1: bitmask pack (ballot) -> 1-bit mask scratch (verbatim champion)
// k2: g^2 on the fly (clz/ffs) + exact early-exit vertical min-plus ->
//     unweighted dt write + int atomicMax(d2); last CTA of slice normalizes.
// Weights {0.5,1,2} are powers of two: (w*a - w*b)/(w*a) == (a-b)/a exactly,
// so the weight cancels bit-exactly and is omitted.

#define HH 256
#define WW 256
#define NPIX (HH * WW)
#define BIG 512
#define MAXSLICES 64
#define WPR 8
#define SLICE_WORDS (HH * WPR)        // 2048

__device__ unsigned int maskbuf[MAXSLICES * SLICE_WORDS];
__device__ int          d2max[MAXSLICES];
__device__ unsigned int ticket[MAXSLICES];        // monotonic, zero-init

// ---------------- Kernel 1: mask pack (champion version, verbatim) ----------------
#define K1_THREADS 256

__global__ __launch_bounds__(K1_THREADS)
void k1_mask(const float* __restrict__ in) {
    const int slice = blockIdx.x >> 4;
    const int rb    = blockIdx.x & 15;
    const int tid   = threadIdx.x;

    if (rb == 0 && tid == 0) d2max[slice] = 0;           // reset before k2

    const float4* s4 = reinterpret_cast<const float4*>(in)
                     + (size_t)slice * (NPIX / 4) + (size_t)rb * 1024 + tid * 4;
    float4 a = s4[0], b = s4[1], c = s4[2], d = s4[3];
    unsigned m = 0;
    m |= (a.x != 0.0f) << 0;  m |= (a.y != 0.0f) << 1;
    m |= (a.z != 0.0f) << 2;  m |= (a.w != 0.0f) << 3;
    m |= (b.x != 0.0f) << 4;  m |= (b.y != 0.0f) << 5;
    m |= (b.z != 0.0f) << 6;  m |= (b.w != 0.0f) << 7;
    m |= (c.x != 0.0f) << 8;  m |= (c.y != 0.0f) << 9;
    m |= (c.z != 0.0f) << 10; m |= (c.w != 0.0f) << 11;
    m |= (d.x != 0.0f) << 12; m |= (d.y != 0.0f) << 13;
    m |= (d.z != 0.0f) << 14; m |= (d.w != 0.0f) << 15;
    unsigned other = __shfl_xor_sync(0xffffffffu, m, 1);
    if ((tid & 1) == 0) {
        maskbuf[slice * SLICE_WORDS + rb * 128 + (tid >> 1)] = m | (other << 16);
    }
}

// ---------------- Kernel 2: pass B + last-CTA normalize ----------------
#define K2_COLS 16
#define K2_THREADS 512

__global__ __launch_bounds__(K2_THREADS)
void k2_passB(float* __restrict__ out) {
    __shared__ unsigned int M[SLICE_WORDS];       // 8 KB: whole-slice bitmask
    __shared__ unsigned int g2[HH * K2_COLS];     // 16 KB: g^2 tile [row][col]
    __shared__ int red[K2_THREADS / 32];          // 16 warps
    __shared__ unsigned int lastFlag;

    const int slice = blockIdx.x >> 4;            // 16 strips per slice
    const int st    = blockIdx.x & 15;
    const int c0    = st * K2_COLS;
    const int tid   = threadIdx.x;

    // load slice bitmask: 4 words/thread
    {
        const unsigned int* src = maskbuf + slice * SLICE_WORDS;
        #pragma unroll
        for (int k = 0; k < SLICE_WORDS / K2_THREADS; ++k)
            M[k * K2_THREADS + tid] = src[k * K2_THREADS + tid];
    }
    __syncthreads();

    // compute g^2 for the strip: 8 px/thread via clz/ffs on row bitmask
    #pragma unroll
    for (int it = 0; it < (HH * K2_COLS) / K2_THREADS; ++it) {
        int i = it * K2_THREADS + tid;
        int r = i >> 4;
        int w = c0 + (i & 15);
        const unsigned int* Mr = M + r * WPR;
        int ci = w >> 5, b = w & 31;

        int ld = BIG;                                          // nearest zero <= w
        unsigned lmask = (b == 31) ? 0xffffffffu : ((2u << b) - 1u);
        unsigned z = (~Mr[ci]) & lmask;
        if (z) {
            ld = b - (31 - __clz(z));
        } else {
            for (int cj = ci - 1; cj >= 0; --cj) {
                unsigned zz = ~Mr[cj];
                if (zz) { ld = (ci - cj) * 32 + b - (31 - __clz(zz)); break; }
            }
        }
        int rd = BIG;                                          // nearest zero >= w
        z = (~Mr[ci]) >> b;
        if (z) {
            rd = __ffs(z) - 1;
        } else {
            for (int cj = ci + 1; cj < WPR; ++cj) {
                unsigned zz = ~Mr[cj];
                if (zz) { rd = cj * 32 + (__ffs(zz) - 1) - w; break; }
            }
        }
        int g = min(min(ld, rd), BIG);
        g2[r * K2_COLS + (i & 15)] = (unsigned)(g * g);
    }
    __syncthreads();

    float* dst = out + (size_t)slice * NPIX;

    int lmax = 0;
    #pragma unroll
    for (int it = 0; it < (HH * K2_COLS) / K2_THREADS; ++it) {
        int i = it * K2_THREADS + tid;
        int r = i >> 4, c = i & 15;
        int best = (int)g2[r * K2_COLS + c];
        for (int d = 1; d < HH; ++d) {
            int dd = d * d;
            if (dd >= best) break;                // exact: candidates are >= d^2
            int up = r - d, dn = r + d;
            if (up >= 0) best = min(best, (int)g2[up * K2_COLS + c] + dd);
            if (dn < HH) best = min(best, (int)g2[dn * K2_COLS + c] + dd);
        }
        dst[r * WW + c0 + c] = sqrtf((float)best);   // unweighted: weight cancels
        lmax = max(lmax, best);
    }

    // per-slice integer d2 max
    lmax = __reduce_max_sync(0xffffffffu, lmax);
    if ((tid & 31) == 0) red[tid >> 5] = lmax;
    __syncthreads();
    if (tid < 16) {
        int v = red[tid];
        #pragma unroll
        for (int o = 8; o; o >>= 1) v = max(v, __shfl_xor_sync(0x0000ffffu, v, o, 16));
        if (tid == 0) atomicMax(&d2max[slice], v);
    }

    // ---- ticket: single-thread release fence (after CTA-scope ordering) ----
    __syncthreads();                               // order ALL threads' dt stores to tid0
    if (tid == 0) {
        __threadfence();                           // release to device scope (cumulative)
        unsigned old = atomicAdd(&ticket[slice], 1u);
        lastFlag = ((old & 15u) == 15u);           // 16 arrivals per slice per replay
        if (lastFlag) __threadfence();             // acquire side
    }
    __syncthreads();

    if (lastFlag) {
        const int   md2 = *(volatile int*)&d2max[slice];
        const float mx  = sqrtf((float)md2);
        const float inv = (md2 > 0) ? (1.0f / mx) : 0.0f;   // md2==0 -> all dt==0 -> out 0
        float4* p = reinterpret_cast<float4*>(out) + (size_t)slice * (NPIX / 4);
        #pragma unroll 8
        for (int k = 0; k < (NPIX / 4) / K2_THREADS; ++k) {  // 32 float4 per thread
            float4 v = __ldcg(p + k * K2_THREADS + tid);     // L1-bypass (peer-written)
            v.x = (mx - v.x) * inv;
            v.y = (mx - v.y) * inv;
            v.z = (mx - v.z) * inv;
            v.w = (mx - v.w) * inv;
            p[k * K2_THREADS + tid] = v;
        }
    }
}

extern "C" void kernel_launch(void* const* d_in, const int* in_sizes, int n_in,
                              void* d_out, int out_size) {
    const float* in = (const float*)d_in[0];
    float* out = (float*)d_out;
    const int nslices = in_sizes[0] / NPIX;       // 48 for [16,3,256,256]

    k1_mask <<<nslices * 16, K1_THREADS>>>(in);
    k2_passB<<<nslices * 16, K2_THREADS>>>(out);
}

// round 14
// speedup vs baseline: 1.4802x; 1.4675x over previous
#include <cuda_runtime.h>

// WeightedDistanceTransform — champion 3-kernel pipeline, two-stream slice split.
// Slices are independent end-to-end, so run half on stream 0 and half on a
// second stream; each stream runs its own k1->k2->k3 chain. Ramp gaps of one
// stream overlap compute of the other. Kernel bodies = R7 champion + slice0.

#define HH 256
#define WW 256
#define NPIX (HH * WW)
#define BIG 512
#define MAXSLICES 64
#define WPR 8
#define SLICE_WORDS (HH * WPR)        // 2048

__device__ unsigned int maskbuf[MAXSLICES * SLICE_WORDS];
__device__ unsigned int mx_bits[MAXSLICES];

// ---------------- Kernel 1: mask pack ----------------
#define K1_THREADS 256

__global__ __launch_bounds__(K1_THREADS)
void k1_mask(const float* __restrict__ in, int slice0) {
    const int slice = slice0 + (blockIdx.x >> 4);
    const int rb    = blockIdx.x & 15;
    const int tid   = threadIdx.x;

    if (rb == 0 && tid == 0) mx_bits[slice] = 0u;        // reset before k2 (same stream)

    const float4* s4 = reinterpret_cast<const float4*>(in)
                     + (size_t)slice * (NPIX / 4) + (size_t)rb * 1024 + tid * 4;
    float4 a = s4[0], b = s4[1], c = s4[2], d = s4[3];
    unsigned m = 0;
    m |= (a.x != 0.0f) << 0;  m |= (a.y != 0.0f) << 1;
    m |= (a.z != 0.0f) << 2;  m |= (a.w != 0.0f) << 3;
    m |= (b.x != 0.0f) << 4;  m |= (b.y != 0.0f) << 5;
    m |= (b.z != 0.0f) << 6;  m |= (b.w != 0.0f) << 7;
    m |= (c.x != 0.0f) << 8;  m |= (c.y != 0.0f) << 9;
    m |= (c.z != 0.0f) << 10; m |= (c.w != 0.0f) << 11;
    m |= (d.x != 0.0f) << 12; m |= (d.y != 0.0f) << 13;
    m |= (d.z != 0.0f) << 14; m |= (d.w != 0.0f) << 15;
    unsigned other = __shfl_xor_sync(0xffffffffu, m, 1);
    if ((tid & 1) == 0) {
        maskbuf[slice * SLICE_WORDS + rb * 128 + (tid >> 1)] = m | (other << 16);
    }
}

// ---------------- Kernel 2: g^2 + vertical min-plus ----------------
#define K2_COLS 16
#define K2_THREADS 512

__global__ __launch_bounds__(K2_THREADS)
void k2_passB(float* __restrict__ out, int slice0) {
    __shared__ unsigned int M[SLICE_WORDS];       // 8 KB: whole-slice bitmask
    __shared__ unsigned int g2[HH * K2_COLS];     // 16 KB: g^2 tile [row][col]
    __shared__ float red[K2_THREADS / 32];        // 16 warps

    const int slice = slice0 + (blockIdx.x >> 4); // 16 strips per slice
    const int st    = blockIdx.x & 15;
    const int c0    = st * K2_COLS;
    const int tid   = threadIdx.x;

    {
        const unsigned int* src = maskbuf + slice * SLICE_WORDS;
        #pragma unroll
        for (int k = 0; k < SLICE_WORDS / K2_THREADS; ++k)
            M[k * K2_THREADS + tid] = src[k * K2_THREADS + tid];
    }
    __syncthreads();

    #pragma unroll
    for (int it = 0; it < (HH * K2_COLS) / K2_THREADS; ++it) {
        int i = it * K2_THREADS + tid;
        int r = i >> 4;
        int w = c0 + (i & 15);
        const unsigned int* Mr = M + r * WPR;
        int ci = w >> 5, b = w & 31;

        int ld = BIG;                                          // nearest zero <= w
        unsigned lmask = (b == 31) ? 0xffffffffu : ((2u << b) - 1u);
        unsigned z = (~Mr[ci]) & lmask;
        if (z) {
            ld = b - (31 - __clz(z));
        } else {
            for (int cj = ci - 1; cj >= 0; --cj) {
                unsigned zz = ~Mr[cj];
                if (zz) { ld = (ci - cj) * 32 + b - (31 - __clz(zz)); break; }
            }
        }
        int rd = BIG;                                          // nearest zero >= w
        z = (~Mr[ci]) >> b;
        if (z) {
            rd = __ffs(z) - 1;
        } else {
            for (int cj = ci + 1; cj < WPR; ++cj) {
                unsigned zz = ~Mr[cj];
                if (zz) { rd = cj * 32 + (__ffs(zz) - 1) - w; break; }
            }
        }
        int g = min(min(ld, rd), BIG);
        g2[r * K2_COLS + (i & 15)] = (unsigned)(g * g);
    }
    __syncthreads();

    const float wts[3] = {0.5f, 1.0f, 2.0f};
    const float wc = wts[slice % 3];
    float* dst = out + (size_t)slice * NPIX;

    float lmax = 0.0f;
    #pragma unroll
    for (int it = 0; it < (HH * K2_COLS) / K2_THREADS; ++it) {
        int i = it * K2_THREADS + tid;
        int r = i >> 4, c = i & 15;
        int best = (int)g2[r * K2_COLS + c];
        for (int d = 1; d < HH; ++d) {
            int dd = d * d;
            if (dd >= best) break;                // exact: candidates are >= d^2
            int up = r - d, dn = r + d;
            if (up >= 0) best = min(best, (int)g2[up * K2_COLS + c] + dd);
            if (dn < HH) best = min(best, (int)g2[dn * K2_COLS + c] + dd);
        }
        float dt = wc * sqrtf((float)best);
        dst[r * WW + c0 + c] = dt;
        lmax = fmaxf(lmax, dt);
    }

    #pragma unroll
    for (int o = 16; o; o >>= 1) lmax = fmaxf(lmax, __shfl_xor_sync(0xffffffffu, lmax, o));
    if ((tid & 31) == 0) red[tid >> 5] = lmax;
    __syncthreads();
    if (tid < 16) {
        float v = red[tid];
        #pragma unroll
        for (int o = 8; o; o >>= 1) v = fmaxf(v, __shfl_xor_sync(0x0000ffffu, v, o, 16));
        if (tid == 0) atomicMax(&mx_bits[slice], __float_as_uint(v));  // dt>=0: bit-monotone
    }
}

// ---------------- Kernel 3: normalize ----------------
#define K3_THREADS 256

__global__ __launch_bounds__(K3_THREADS)
void k3_norm(float* __restrict__ out, int slice0) {
    const int slice = slice0 + (blockIdx.x >> 4);
    const int bl    = blockIdx.x & 15;
    const float mx  = __uint_as_float(mx_bits[slice]);
    const float inv = (mx > 0.0f) ? (1.0f / mx) : 0.0f;   // mx==0 -> dt==0 -> out 0

    float4* p = reinterpret_cast<float4*>(out) + (size_t)slice * (NPIX / 4) + bl * 1024;
    #pragma unroll
    for (int k = 0; k < 4; ++k) {
        int j = k * K3_THREADS + threadIdx.x;
        float4 v = p[j];
        v.x = (mx - v.x) * inv;
        v.y = (mx - v.y) * inv;
        v.z = (mx - v.z) * inv;
        v.w = (mx - v.w) * inv;
        p[j] = v;
    }
}

extern "C" void kernel_launch(void* const* d_in, const int* in_sizes, int n_in,
                              void* d_out, int out_size) {
    const float* in = (const float*)d_in[0];
    float* out = (float*)d_out;
    const int nslices = in_sizes[0] / NPIX;       // 48 for [16,3,256,256]

    // One-time side stream + fork/join events (no device memory involved).
    static cudaStream_t sB = nullptr;
    static cudaEvent_t  eFork = nullptr, eJoin = nullptr;
    if (sB == nullptr) {
        cudaStreamCreateWithFlags(&sB, cudaStreamNonBlocking);
        cudaEventCreateWithFlags(&eFork, cudaEventDisableTiming);
        cudaEventCreateWithFlags(&eJoin, cudaEventDisableTiming);
    }

    const int nA = (nslices + 1) / 2;             // group A: [0, nA)
    const int nB = nslices - nA;                  // group B: [nA, nslices)

    if (nB > 0) {
        // fork: stream B joins the captured stream's dependency graph
        cudaEventRecord(eFork, 0);
        cudaStreamWaitEvent(sB, eFork, 0);
    }

    // group A chain on the captured (default) stream
    k1_mask <<<nA * 16, K1_THREADS, 0, 0>>>(in,  0);
    k2_passB<<<nA * 16, K2_THREADS, 0, 0>>>(out, 0);
    k3_norm <<<nA * 16, K3_THREADS, 0, 0>>>(out, 0);

    if (nB > 0) {
        // group B chain on the side stream
        k1_mask <<<nB * 16, K1_THREADS, 0, sB>>>(in,  nA);
        k2_passB<<<nB * 16, K2_THREADS, 0, sB>>>(out, nA);
        k3_norm <<<nB * 16, K3_THREADS, 0, sB>>>(out, nA);

        // join: captured stream waits for stream B
        cudaEventRecord(eJoin, sB);
        cudaStreamWaitEvent(0, eJoin, 0);
    }
}